// round 7
// baseline (speedup 1.0000x reference)
#include <cuda_runtime.h>

// LSTMForecastModel: B=4096, T=128, OUT=64, H=200, 2-layer encoder + 2-layer decoder + linear head.
// Batch rows are independent through the whole recurrence -> each CTA owns 32 rows,
// runs the entire sequence privately. No grid sync, no inter-CTA traffic except
// read-only weights streamed from L2.
//
// Launch 1 (prep): transpose/permute weights into [k][unit][gate] layout so the
// inner GEMM loop does one coalesced LDG.128 per thread per k.
// Launch 2 (main): 128 CTAs x 800 threads. Thread (tx=unit 0..199, ty=rowblk 0..3)
// owns an 8-row x 4-gate accumulator tile; c-state lives in registers for the
// whole kernel; h lives in smem as [k][row] for broadcast LDS.128 reads.

#define BATCH  4096
#define TLEN   128
#define OUTLEN 64
#define HID    200
#define G4     800      // 4*H
#define MCTA   32       // rows per CTA
#define NTHR   800      // 200 units * 4 row-blocks
#define NBLK   128      // 4096/32
#define WSZ    (HID * G4)   // 160000 elements per weight matrix

// Permuted weights: index [k*800 + unit*4 + gate], gate order (i,f,g,o).
// Order: 0=enc_Whh0, 1=enc_Wih1, 2=enc_Whh1, 3=dec_Whh0, 4=dec_Wih1, 5=dec_Whh1
__device__ float g_W[6][WSZ];
// Permuted vectors [unit*4+gate]: 0=enc_Wih0, 1=enc_b0, 2=enc_b1, 3=dec_Wih0, 4=dec_b0, 5=dec_b1
__device__ float g_v[6][G4];

__global__ void prep_kernel(const float* __restrict__ eWhh0, const float* __restrict__ eWih1,
                            const float* __restrict__ eWhh1, const float* __restrict__ dWhh0,
                            const float* __restrict__ dWih1, const float* __restrict__ dWhh1,
                            const float* __restrict__ eWih0, const float* __restrict__ eb0,
                            const float* __restrict__ eb1,  const float* __restrict__ dWih0,
                            const float* __restrict__ db0,  const float* __restrict__ db1)
{
    int i = blockIdx.x * blockDim.x + threadIdx.x;
    if (i < WSZ) {
        int k    = i / G4;
        int rest = i - k * G4;
        int u    = rest >> 2;
        int g    = rest & 3;
        // source: W is (4H, H) row-major; row for gate g, unit u is g*H+u
        int s = (g * HID + u) * HID + k;
        g_W[0][i] = eWhh0[s];
        g_W[1][i] = eWih1[s];
        g_W[2][i] = eWhh1[s];
        g_W[3][i] = dWhh0[s];
        g_W[4][i] = dWih1[s];
        g_W[5][i] = dWhh1[s];
    }
    if (i < G4) {
        int u = i >> 2, g = i & 3;
        int s = g * HID + u;
        g_v[0][i] = eWih0[s];   // (4H,1) -> flat 800
        g_v[1][i] = eb0[s];
        g_v[2][i] = eb1[s];
        g_v[3][i] = dWih0[s];
        g_v[4][i] = db0[s];
        g_v[5][i] = db1[s];
    }
}

__device__ __forceinline__ float sigf(float x)   { return __fdividef(1.f, 1.f + __expf(-x)); }
__device__ __forceinline__ float tanh_f(float x) { return 1.f - __fdividef(2.f, 1.f + __expf(2.f * x)); }

struct Acc { float i[8]; float f[8]; float g[8]; float o[8]; };

__device__ __forceinline__ void acc_init(Acc& a, const float* __restrict__ bias, int tx)
{
    float4 bv = reinterpret_cast<const float4*>(bias)[tx];
#pragma unroll
    for (int rr = 0; rr < 8; rr++) {
        a.i[rr] = bv.x; a.f[rr] = bv.y; a.g[rr] = bv.z; a.o[rr] = bv.w;
    }
}

__device__ __forceinline__ void acc_rank1(Acc& a, const float* __restrict__ wx, int tx,
                                          const float xr[8])
{
    float4 wv = reinterpret_cast<const float4*>(wx)[tx];
#pragma unroll
    for (int rr = 0; rr < 8; rr++) {
        a.i[rr] += wv.x * xr[rr];
        a.f[rr] += wv.y * xr[rr];
        a.g[rr] += wv.z * xr[rr];
        a.o[rr] += wv.w * xr[rr];
    }
}

// gates[r][g*H+u] += sum_k h[r][k] * W[g*H+u][k]; W permuted as [k][u][g] (float4 per (k,u)),
// h in smem as [k][row] (32 rows = 8 float4 per k).
__device__ __forceinline__ void gemm_pass(const float* __restrict__ W, const float* __restrict__ hs,
                                          int tx, int ty, Acc& a)
{
    const float4* __restrict__ w4 = reinterpret_cast<const float4*>(W) + tx;
    const float4* __restrict__ h4 = reinterpret_cast<const float4*>(hs) + ty * 2;
#pragma unroll 2
    for (int k = 0; k < HID; k++) {
        float4 wv = w4[k * HID];       // 200 float4 per k-row
        float4 ha = h4[k * 8];
        float4 hb = h4[k * 8 + 1];
        float hr[8] = {ha.x, ha.y, ha.z, ha.w, hb.x, hb.y, hb.z, hb.w};
#pragma unroll
        for (int rr = 0; rr < 8; rr++) {
            a.i[rr] += wv.x * hr[rr];
            a.f[rr] += wv.y * hr[rr];
            a.g[rr] += wv.z * hr[rr];
            a.o[rr] += wv.w * hr[rr];
        }
    }
}

__device__ __forceinline__ void cell_epi(Acc& a, float c[8], float* __restrict__ hdst,
                                         int tx, int ty)
{
#pragma unroll
    for (int rr = 0; rr < 8; rr++) {
        float ig = sigf(a.i[rr]);
        float fg = sigf(a.f[rr]);
        float gg = tanh_f(a.g[rr]);
        float og = sigf(a.o[rr]);
        float cn = fg * c[rr] + ig * gg;
        c[rr]    = cn;
        hdst[tx * 32 + ty * 8 + rr] = og * tanh_f(cn);
    }
}

// smem layout (floats): h0[6400] h1[6400] xs[4096] vb[4800] lin[200] inp[32] = 21928 floats
#define SMEM_FLOATS 21928

__global__ void __launch_bounds__(NTHR, 1)
lstm_kernel(const float* __restrict__ x, const float* __restrict__ linW,
            const float* __restrict__ linb, float* __restrict__ out)
{
    extern __shared__ float sm[];
    float* h0    = sm;            // [k=200][row=32]
    float* h1    = sm + 6400;
    float* xs    = sm + 12800;    // [row=32][t=128]
    float* vb    = sm + 16896;    // 6 x 800
    float* lin_s = sm + 21696;    // 200
    float* inp_s = sm + 21896;    // 32

    const int tid  = threadIdx.x;
    const int ty   = tid & 3;     // row-block 0..3 (8 rows each)
    const int tx   = tid >> 2;    // hidden unit 0..199
    const int row0 = blockIdx.x * MCTA;

    // stage / init
    for (int i = tid; i < 12800; i += NTHR) sm[i] = 0.f;               // h0,h1 = 0
    for (int i = tid; i < MCTA * TLEN; i += NTHR) {
        int r = i >> 7, t = i & (TLEN - 1);
        xs[i] = x[(row0 + r) * TLEN + t];
    }
    {
        const float* gv = &g_v[0][0];
        for (int i = tid; i < 6 * G4; i += NTHR) vb[i] = gv[i];
    }
    for (int i = tid; i < HID; i += NTHR) lin_s[i] = linW[i];
    __syncthreads();

    float c0[8], c1[8];
#pragma unroll
    for (int rr = 0; rr < 8; rr++) { c0[rr] = 0.f; c1[rr] = 0.f; }

    const float* wx0  = vb;
    const float* b0   = vb + 800;
    const float* b1   = vb + 1600;
    const float* dwx0 = vb + 2400;
    const float* db0  = vb + 3200;
    const float* db1  = vb + 4000;

    // ---------------- encoder: 128 steps, 2 layers ----------------
    for (int t = 0; t < TLEN; t++) {
        // layer 0: input = scalar x[:,t] (rank-1), recurrence Whh0
        Acc a;
        acc_init(a, b0, tx);
        {
            float xr[8];
#pragma unroll
            for (int rr = 0; rr < 8; rr++) xr[rr] = xs[(ty * 8 + rr) * TLEN + t];
            acc_rank1(a, wx0, tx, xr);
        }
        gemm_pass(g_W[0], h0, tx, ty, a);
        __syncthreads();                 // everyone done reading old h0
        cell_epi(a, c0, h0, tx, ty);     // write new h0 (= ys1[t])
        __syncthreads();

        // layer 1: input = new h0 via Wih1, recurrence Whh1
        Acc b_;
        acc_init(b_, b1, tx);
        gemm_pass(g_W[1], h0, tx, ty, b_);
        gemm_pass(g_W[2], h1, tx, ty, b_);
        __syncthreads();                 // done reading old h1
        cell_epi(b_, c1, h1, tx, ty);
        __syncthreads();
    }

    // decoder initial input = x[:, T-1]
    if (ty == 0 && tx < MCTA) inp_s[tx] = xs[tx * TLEN + (TLEN - 1)];
    __syncthreads();

    const float lb = linb[0];

    // ---------------- decoder: 64 steps, 2 layers + linear head ----------------
    // carry: (h0,c0) continue from encoder layer0 final state; (h1,c1) from layer1 final.
    for (int t = 0; t < OUTLEN; t++) {
        Acc a;
        acc_init(a, db0, tx);
        {
            float xr[8];
#pragma unroll
            for (int rr = 0; rr < 8; rr++) xr[rr] = inp_s[ty * 8 + rr];
            acc_rank1(a, dwx0, tx, xr);
        }
        gemm_pass(g_W[3], h0, tx, ty, a);
        __syncthreads();
        cell_epi(a, c0, h0, tx, ty);
        __syncthreads();

        Acc b_;
        acc_init(b_, db1, tx);
        gemm_pass(g_W[4], h0, tx, ty, b_);   // input = new h0 (dec layer0 output)
        gemm_pass(g_W[5], h1, tx, ty, b_);
        __syncthreads();
        cell_epi(b_, c1, h1, tx, ty);
        __syncthreads();

        // pred = h1 @ lin_W.T + lin_b ; feed back as next input
        if (ty == 0 && tx < MCTA) {
            float s = lb;
            for (int u = 0; u < HID; u++) s += lin_s[u] * h1[u * 32 + tx];
            out[(row0 + tx) * OUTLEN + t] = s;
            inp_s[tx] = s;
        }
        __syncthreads();
    }
}

extern "C" void kernel_launch(void* const* d_in, const int* in_sizes, int n_in,
                              void* d_out, int out_size)
{
    (void)in_sizes; (void)n_in; (void)out_size;
    const float* x     = (const float*)d_in[0];
    const float* eWih0 = (const float*)d_in[1];
    const float* eWhh0 = (const float*)d_in[2];
    const float* eb0   = (const float*)d_in[3];
    const float* eWih1 = (const float*)d_in[4];
    const float* eWhh1 = (const float*)d_in[5];
    const float* eb1   = (const float*)d_in[6];
    const float* dWih0 = (const float*)d_in[7];
    const float* dWhh0 = (const float*)d_in[8];
    const float* db0   = (const float*)d_in[9];
    const float* dWih1 = (const float*)d_in[10];
    const float* dWhh1 = (const float*)d_in[11];
    const float* db1   = (const float*)d_in[12];
    const float* linW  = (const float*)d_in[13];
    const float* linb  = (const float*)d_in[14];
    float* out = (float*)d_out;

    // idempotent, deterministic; required for 88KB dynamic smem
    cudaFuncSetAttribute(lstm_kernel, cudaFuncAttributeMaxDynamicSharedMemorySize,
                         SMEM_FLOATS * (int)sizeof(float));

    prep_kernel<<<(WSZ + 255) / 256, 256>>>(eWhh0, eWih1, eWhh1, dWhh0, dWih1, dWhh1,
                                            eWih0, eb0, eb1, dWih0, db0, db1);
    lstm_kernel<<<NBLK, NTHR, SMEM_FLOATS * (int)sizeof(float)>>>(x, linW, linb, out);
}

// round 8
// speedup vs baseline: 1.1312x; 1.1312x over previous
#include <cuda_runtime.h>

// LSTMForecastModel: B=4096, T=128, OUT=64, H=200.
// R7: packed fp32x2 FMA (fma.rn.f32x2) -> 128 MAC/cyc/SM instead of 64.
// Thread tile = 2 units x 4 rows x 4 gates; weights pre-interleaved as
// (unitA, unitB) pairs so the packed multiplier loads with zero pack MOVs.
// c-state lives in smem (paired layout) to keep regs <= 80 at 800 thr/CTA.

#define BATCH  4096
#define TLEN   128
#define OUTLEN 64
#define HID    200
#define G4     800
#define MCTA   32
#define NTHR   800      // 100 unit-pairs * 8 row-blocks(4 rows)
#define NBLK   128
#define WSZ    (HID * G4)

typedef unsigned long long u64;

// Paired weights: index [k*800 + up*8 + g*2 + half], g in (i,f,g,o), half: 0 -> unit=up, 1 -> unit=up+100.
// 0=enc_Whh0, 1=enc_Wih1, 2=enc_Whh1, 3=dec_Whh0, 4=dec_Wih1, 5=dec_Whh1
__device__ float g_W[6][WSZ];
// Paired vectors [up*8 + g*2 + half]: 0=enc_Wih0, 1=enc_b0, 2=enc_b1, 3=dec_Wih0, 4=dec_b0, 5=dec_b1
__device__ float g_v[6][G4];

__global__ void prep_kernel(const float* __restrict__ eWhh0, const float* __restrict__ eWih1,
                            const float* __restrict__ eWhh1, const float* __restrict__ dWhh0,
                            const float* __restrict__ dWih1, const float* __restrict__ dWhh1,
                            const float* __restrict__ eWih0, const float* __restrict__ eb0,
                            const float* __restrict__ eb1,  const float* __restrict__ dWih0,
                            const float* __restrict__ db0,  const float* __restrict__ db1)
{
    int i = blockIdx.x * blockDim.x + threadIdx.x;
    if (i < WSZ) {
        int k    = i / G4;
        int rest = i - k * G4;
        int up   = rest >> 3;
        int q    = rest & 7;
        int g    = q >> 1;
        int u    = up + (q & 1) * 100;
        int s = (g * HID + u) * HID + k;
        g_W[0][i] = eWhh0[s];
        g_W[1][i] = eWih1[s];
        g_W[2][i] = eWhh1[s];
        g_W[3][i] = dWhh0[s];
        g_W[4][i] = dWih1[s];
        g_W[5][i] = dWhh1[s];
    }
    if (i < G4) {
        int up = i >> 3, q = i & 7;
        int g  = q >> 1;
        int u  = up + (q & 1) * 100;
        int s  = g * HID + u;
        g_v[0][i] = eWih0[s];
        g_v[1][i] = eb0[s];
        g_v[2][i] = eb1[s];
        g_v[3][i] = dWih0[s];
        g_v[4][i] = db0[s];
        g_v[5][i] = db1[s];
    }
}

// ---- packed f32x2 primitives ----
__device__ __forceinline__ void fma2(u64& d, u64 a, u64 b) {
    asm("fma.rn.f32x2 %0, %1, %2, %0;" : "+l"(d) : "l"(a), "l"(b));
}
__device__ __forceinline__ u64 dup2(float w) {
    u64 r; unsigned wb = __float_as_uint(w);
    asm("mov.b64 %0, {%1, %1};" : "=l"(r) : "r"(wb));
    return r;
}
__device__ __forceinline__ u64 pk2(float lo, float hi) {
    u64 r;
    asm("mov.b64 %0, {%1, %2};" : "=l"(r) : "r"(__float_as_uint(lo)), "r"(__float_as_uint(hi)));
    return r;
}
__device__ __forceinline__ float2 unpk(u64 v) {
    unsigned lo, hi;
    asm("mov.b64 {%0, %1}, %2;" : "=r"(lo), "=r"(hi) : "l"(v));
    return make_float2(__uint_as_float(lo), __uint_as_float(hi));
}

__device__ __forceinline__ float sigf(float x)   { return __fdividef(1.f, 1.f + __expf(-x)); }
__device__ __forceinline__ float tanh_f(float x) { return 1.f - __fdividef(2.f, 1.f + __expf(2.f * x)); }

// acc[g][r]: pair = (unit txp, unit txp+100); r = row within this thread's 4-row block.
__device__ __forceinline__ void acc_init2(u64 acc[4][4], const float* __restrict__ vbase, int txp)
{
    const ulonglong2* b2 = reinterpret_cast<const ulonglong2*>(vbase) + txp * 2;
    ulonglong2 bv1 = b2[0];   // (i pair, f pair)
    ulonglong2 bv2 = b2[1];   // (g pair, o pair)
#pragma unroll
    for (int r = 0; r < 4; r++) {
        acc[0][r] = bv1.x; acc[1][r] = bv1.y; acc[2][r] = bv2.x; acc[3][r] = bv2.y;
    }
}

__device__ __forceinline__ void acc_rank1_2(u64 acc[4][4], const float* __restrict__ wxbase,
                                            int txp, const u64 xr[4])
{
    const ulonglong2* w2 = reinterpret_cast<const ulonglong2*>(wxbase) + txp * 2;
    ulonglong2 wv1 = w2[0];
    ulonglong2 wv2 = w2[1];
#pragma unroll
    for (int r = 0; r < 4; r++) {
        fma2(acc[0][r], wv1.x, xr[r]);
        fma2(acc[1][r], wv1.y, xr[r]);
        fma2(acc[2][r], wv2.x, xr[r]);
        fma2(acc[3][r], wv2.y, xr[r]);
    }
}

// gates += h @ W^T; W paired [k][up][g][half], h in smem [k][row32].
__device__ __forceinline__ void gemm_pass2(const float* __restrict__ W, const float* __restrict__ hs,
                                           int txp, int ty, u64 acc[4][4])
{
    const ulonglong2* __restrict__ w2 = reinterpret_cast<const ulonglong2*>(W) + txp * 2;
    const float4*     __restrict__ h4 = reinterpret_cast<const float4*>(hs) + ty;
#pragma unroll 2
    for (int k = 0; k < HID; k++) {
        ulonglong2 wv1 = w2[k * 200];       // (iA,iB),(fA,fB)
        ulonglong2 wv2 = w2[k * 200 + 1];   // (gA,gB),(oA,oB)
        float4 hv = h4[k * 8];              // 4 rows of h[k]
        u64 hr0 = dup2(hv.x), hr1 = dup2(hv.y), hr2 = dup2(hv.z), hr3 = dup2(hv.w);
        fma2(acc[0][0], wv1.x, hr0); fma2(acc[1][0], wv1.y, hr0);
        fma2(acc[2][0], wv2.x, hr0); fma2(acc[3][0], wv2.y, hr0);
        fma2(acc[0][1], wv1.x, hr1); fma2(acc[1][1], wv1.y, hr1);
        fma2(acc[2][1], wv2.x, hr1); fma2(acc[3][1], wv2.y, hr1);
        fma2(acc[0][2], wv1.x, hr2); fma2(acc[1][2], wv1.y, hr2);
        fma2(acc[2][2], wv2.x, hr2); fma2(acc[3][2], wv2.y, hr2);
        fma2(acc[0][3], wv1.x, hr3); fma2(acc[1][3], wv1.y, hr3);
        fma2(acc[2][3], wv2.x, hr3); fma2(acc[3][3], wv2.y, hr3);
    }
}

// c kept in smem as u64 pairs: index [txp*32 + ty*4 + r] (pair = unitA, unitB).
// h written back to [u][row32] float layout (unchanged for gemm reads + head).
__device__ __forceinline__ void cell_epi2(u64 acc[4][4], float* __restrict__ cs,
                                          float* __restrict__ hdst, int txp, int ty)
{
    u64* cp = reinterpret_cast<u64*>(cs) + txp * 32 + ty * 4;
    float hA[4], hB[4];
#pragma unroll
    for (int r = 0; r < 4; r++) {
        float2 iv = unpk(acc[0][r]);
        float2 fv = unpk(acc[1][r]);
        float2 gv = unpk(acc[2][r]);
        float2 ov = unpk(acc[3][r]);
        float2 cv = unpk(cp[r]);
        float cA = sigf(fv.x) * cv.x + sigf(iv.x) * tanh_f(gv.x);
        float cB = sigf(fv.y) * cv.y + sigf(iv.y) * tanh_f(gv.y);
        cp[r] = pk2(cA, cB);
        hA[r] = sigf(ov.x) * tanh_f(cA);
        hB[r] = sigf(ov.y) * tanh_f(cB);
    }
    *reinterpret_cast<float4*>(hdst + txp * 32 + ty * 4)         = make_float4(hA[0], hA[1], hA[2], hA[3]);
    *reinterpret_cast<float4*>(hdst + (txp + 100) * 32 + ty * 4) = make_float4(hB[0], hB[1], hB[2], hB[3]);
}

// smem floats: h0 6400 | h1 6400 | c0 6400 | c1 6400 | xs 4096 | vb 4800 | lin 200 | inp 32
#define SMEM_FLOATS 34728

__global__ void __launch_bounds__(NTHR, 1)
lstm_kernel(const float* __restrict__ x, const float* __restrict__ linW,
            const float* __restrict__ linb, float* __restrict__ out)
{
    extern __shared__ float sm[];
    float* h0    = sm;
    float* h1    = sm + 6400;
    float* c0s   = sm + 12800;
    float* c1s   = sm + 19200;
    float* xs    = sm + 25600;    // [t][row32]
    float* vb    = sm + 29696;
    float* lin_s = sm + 34496;
    float* inp_s = sm + 34696;

    const int tid  = threadIdx.x;
    const int ty   = tid & 7;     // row-block of 4 rows
    const int txp  = tid >> 3;    // unit-pair 0..99 (units txp, txp+100)
    const int row0 = blockIdx.x * MCTA;

    for (int i = tid; i < 25600; i += NTHR) sm[i] = 0.f;               // h0,h1,c0,c1
    for (int i = tid; i < MCTA * TLEN; i += NTHR) {
        int t = i >> 5, r = i & 31;
        xs[t * 32 + r] = x[(row0 + r) * TLEN + t];
    }
    {
        const float* gv = &g_v[0][0];
        for (int i = tid; i < 6 * G4; i += NTHR) vb[i] = gv[i];
    }
    for (int i = tid; i < HID; i += NTHR) lin_s[i] = linW[i];
    __syncthreads();

    const float* wx0  = vb;
    const float* b0   = vb + 800;
    const float* b1   = vb + 1600;
    const float* dwx0 = vb + 2400;
    const float* db0  = vb + 3200;
    const float* db1  = vb + 4000;

    // ---------------- encoder: 128 steps ----------------
    for (int t = 0; t < TLEN; t++) {
        u64 acc[4][4];
        acc_init2(acc, b0, txp);
        {
            float4 xv = reinterpret_cast<const float4*>(xs + t * 32)[ty];
            u64 xr[4] = {dup2(xv.x), dup2(xv.y), dup2(xv.z), dup2(xv.w)};
            acc_rank1_2(acc, wx0, txp, xr);
        }
        gemm_pass2(g_W[0], h0, txp, ty, acc);
        __syncthreads();
        cell_epi2(acc, c0s, h0, txp, ty);
        __syncthreads();

        u64 accb[4][4];
        acc_init2(accb, b1, txp);
        gemm_pass2(g_W[1], h0, txp, ty, accb);
        gemm_pass2(g_W[2], h1, txp, ty, accb);
        __syncthreads();
        cell_epi2(accb, c1s, h1, txp, ty);
        __syncthreads();
    }

    // decoder initial input = x[:, T-1]
    if (tid < MCTA) inp_s[tid] = xs[(TLEN - 1) * 32 + tid];
    __syncthreads();

    const float lb = linb[0];

    // ---------------- decoder: 64 steps ----------------
    for (int t = 0; t < OUTLEN; t++) {
        u64 acc[4][4];
        acc_init2(acc, db0, txp);
        {
            float4 xv = reinterpret_cast<const float4*>(inp_s)[ty];
            u64 xr[4] = {dup2(xv.x), dup2(xv.y), dup2(xv.z), dup2(xv.w)};
            acc_rank1_2(acc, dwx0, txp, xr);
        }
        gemm_pass2(g_W[3], h0, txp, ty, acc);
        __syncthreads();
        cell_epi2(acc, c0s, h0, txp, ty);
        __syncthreads();

        u64 accb[4][4];
        acc_init2(accb, db1, txp);
        gemm_pass2(g_W[4], h0, txp, ty, accb);
        gemm_pass2(g_W[5], h1, txp, ty, accb);
        __syncthreads();
        cell_epi2(accb, c1s, h1, txp, ty);
        __syncthreads();

        // linear head: pred = h1 @ lin_W.T + lin_b, feed back
        if (tid < MCTA) {
            float s = lb;
            for (int u = 0; u < HID; u++) s += lin_s[u] * h1[u * 32 + tid];
            out[(row0 + tid) * OUTLEN + t] = s;
            inp_s[tid] = s;
        }
        __syncthreads();
    }
}

extern "C" void kernel_launch(void* const* d_in, const int* in_sizes, int n_in,
                              void* d_out, int out_size)
{
    (void)in_sizes; (void)n_in; (void)out_size;
    const float* x     = (const float*)d_in[0];
    const float* eWih0 = (const float*)d_in[1];
    const float* eWhh0 = (const float*)d_in[2];
    const float* eb0   = (const float*)d_in[3];
    const float* eWih1 = (const float*)d_in[4];
    const float* eWhh1 = (const float*)d_in[5];
    const float* eb1   = (const float*)d_in[6];
    const float* dWih0 = (const float*)d_in[7];
    const float* dWhh0 = (const float*)d_in[8];
    const float* db0   = (const float*)d_in[9];
    const float* dWih1 = (const float*)d_in[10];
    const float* dWhh1 = (const float*)d_in[11];
    const float* db1   = (const float*)d_in[12];
    const float* linW  = (const float*)d_in[13];
    const float* linb  = (const float*)d_in[14];
    float* out = (float*)d_out;

    cudaFuncSetAttribute(lstm_kernel, cudaFuncAttributeMaxDynamicSharedMemorySize,
                         SMEM_FLOATS * (int)sizeof(float));

    prep_kernel<<<(WSZ + 255) / 256, 256>>>(eWhh0, eWih1, eWhh1, dWhh0, dWih1, dWhh1,
                                            eWih0, eb0, eb1, dWih0, db0, db1);
    lstm_kernel<<<NBLK, NTHR, SMEM_FLOATS * (int)sizeof(float)>>>(x, linW, linb, out);
}